// round 1
// baseline (speedup 1.0000x reference)
#include <cuda_runtime.h>

// ---------------------------------------------------------------------------
// Problem constants (from reference): N=512, MAX_DIST=16, H=32, N_SPATIAL=64,
// BOND_TYPES=32.
//
// Key restructure: edge_sum[i,j,k] = sum_d T[d][edge_input[i,j,d]][k]
// with T[d] = edge_table @ W[d]  (16 x 32 x 32 = 64KB, precomputed once per
// launch by a tiny kernel into a __device__ global, then staged to smem).
// T is stored TRANSPOSED as Tt[d][k][e] so the smem bank index equals e
// (conflict-free / broadcast for the per-lane gather).
// ---------------------------------------------------------------------------

#define NN      512
#define PAIRS   (NN * NN)           // 262144
#define MAXD    16
#define H       32
#define NSPAT   64
#define T_ELEMS (MAXD * H * H)      // 16384 floats = 64KB
#define SPD_ELEMS (NSPAT * H)       // 2048 floats = 8KB
#define SMEM_BYTES ((T_ELEMS + SPD_ELEMS) * 4)   // 73728

__device__ float g_T[T_ELEMS];      // Tt[d][k][e] = sum_h edge_table[e,h]*W[d,h,k]

__global__ void precompute_T_kernel(const float* __restrict__ edge_table,
                                    const float* __restrict__ W) {
    int idx = blockIdx.x * blockDim.x + threadIdx.x;
    if (idx >= T_ELEMS) return;
    int e = idx & 31;
    int k = (idx >> 5) & 31;
    int d = idx >> 10;
    float s = 0.0f;
#pragma unroll
    for (int h = 0; h < H; ++h)
        s += edge_table[e * H + h] * W[d * (H * H) + h * H + k];
    g_T[d * (H * H) + k * H + e] = s;   // transposed layout [d][k][e]
}

__global__ __launch_bounds__(256)
void bond_encoding_kernel(const int* __restrict__ spatial_pos,
                          const int* __restrict__ edge_input,
                          const float* __restrict__ spd_table,
                          float* __restrict__ out) {
    extern __shared__ float sh[];
    float* shT = sh;                 // 16384 floats: Tt[d][k][e]
    float* shS = sh + T_ELEMS;       // 2048 floats: spd transposed [k][sp]

    // Stage T (vectorized, coalesced)
    {
        const float4* src = (const float4*)g_T;
        float4* dst = (float4*)shT;
        for (int i = threadIdx.x; i < T_ELEMS / 4; i += blockDim.x)
            dst[i] = src[i];
    }
    // Stage spd_table transposed: shS[k*64 + sp] = spd_table[sp*32 + k]
    for (int i = threadIdx.x; i < SPD_ELEMS; i += blockDim.x) {
        int sp = i >> 5;
        int k  = i & 31;
        shS[k * NSPAT + sp] = spd_table[i];
    }
    __syncthreads();

    const int n_tiles = PAIRS / 256;  // 1024
    for (int tile = blockIdx.x; tile < n_tiles; tile += gridDim.x) {
        int pair = tile * 256 + threadIdx.x;   // pair = i*512 + j

        // 16 edge indices as 4 x int4 (64B aligned: pair*16 ints)
        const int4* ep = (const int4*)(edge_input) + pair * 4;
        int4 e0 = ep[0], e1 = ep[1], e2 = ep[2], e3 = ep[3];
        int es[MAXD] = { e0.x, e0.y, e0.z, e0.w,
                         e1.x, e1.y, e1.z, e1.w,
                         e2.x, e2.y, e2.z, e2.w,
                         e3.x, e3.y, e3.z, e3.w };

        float acc[H];
#pragma unroll
        for (int k = 0; k < H; ++k) acc[k] = 0.0f;

#pragma unroll
        for (int d = 0; d < MAXD; ++d) {
            const float* p = shT + d * (H * H) + es[d];   // bank = es[d]: conflict-free
#pragma unroll
            for (int k = 0; k < H; ++k)
                acc[k] += p[k * H];
        }

        int sp = spatial_pos[pair];
        float rden = (sp == 0) ? 1.0f : (1.0f / (float)sp);

        // phi_spd at out[k*262144 + pair], phi_edge at out[8388608 + ...]
        // lane-consecutive pair -> every store fully coalesced (128B lines)
#pragma unroll
        for (int k = 0; k < H; ++k) {
            out[k * PAIRS + pair] = shS[k * NSPAT + sp];
            out[H * PAIRS + k * PAIRS + pair] = acc[k] * rden;
        }
    }
}

extern "C" void kernel_launch(void* const* d_in, const int* in_sizes, int n_in,
                              void* d_out, int out_size) {
    // Map inputs by element count (all distinct):
    //   spatial_pos 262144 (i32), edge_input 4194304 (i32), max_dist 1 (unused),
    //   spd_table 2048 (f32), edge_table 1024 (f32), edge_dis_weight 65536 (f32)
    const int*   spatial_pos = nullptr;
    const int*   edge_input  = nullptr;
    const float* spd_table   = nullptr;
    const float* edge_table  = nullptr;
    const float* W           = nullptr;
    for (int i = 0; i < n_in; ++i) {
        switch (in_sizes[i]) {
            case PAIRS:          spatial_pos = (const int*)d_in[i];   break;
            case PAIRS * MAXD:   edge_input  = (const int*)d_in[i];   break;
            case SPD_ELEMS:      spd_table   = (const float*)d_in[i]; break;
            case H * H:          edge_table  = (const float*)d_in[i]; break;
            case NSPAT * H * H:  W           = (const float*)d_in[i]; break;
            default: break;
        }
    }

    precompute_T_kernel<<<(T_ELEMS + 255) / 256, 256>>>(edge_table, W);

    cudaFuncSetAttribute(bond_encoding_kernel,
                         cudaFuncAttributeMaxDynamicSharedMemorySize, SMEM_BYTES);
    // 3 blocks/SM (72KB smem each) * 148 SMs = 444 persistent blocks
    bond_encoding_kernel<<<444, 256, SMEM_BYTES>>>(
        spatial_pos, edge_input, spd_table, (float*)d_out);
}

// round 2
// speedup vs baseline: 1.1027x; 1.1027x over previous
#include <cuda_runtime.h>
#include <cuda_fp16.h>

// ---------------------------------------------------------------------------
// N=512, MAX_DIST=16, H=32, N_SPATIAL=64, BOND_TYPES=32.
//
// edge_sum[i,j,k] = sum_d T[d][edge_input[i,j,d]][k],  T[d] = edge_table @ W[d].
// T is precomputed once (fp32 math) and stored as fp16 half2 packed over k:
//   g_T2[(d*16 + k2)*32 + e] = half2( T[d][e][2k2], T[d][e][2k2+1] )
// In smem the word-bank index of that layout is e -> conflict-free (or
// broadcast) scalar LDS for the per-lane gather. fp16 halves the crossbar
// traffic (the measured bottleneck); accumulation stays fp32.
// ---------------------------------------------------------------------------

#define NN        512
#define PAIRS     (NN * NN)          // 262144
#define MAXD      16
#define H         32
#define NSPAT     64
#define T2_ELEMS  (MAXD * 16 * 32)   // 8192 half2 = 32KB
#define SPD_ELEMS (NSPAT * H)        // 2048 floats = 8KB
#define SMEM_BYTES (T2_ELEMS * 4 + SPD_ELEMS * 4)   // 40960

#define N_TILES   (PAIRS / 256)      // 1024 pair-tiles of 256
#define N_TASKS   (N_TILES * 2)      // k split in halves -> 2048 tasks
#define GRID      740                // 5 blocks/SM * 148 SMs

__device__ __half2 g_T2[T2_ELEMS];

__global__ void precompute_T_kernel(const float* __restrict__ edge_table,
                                    const float* __restrict__ W) {
    int idx = blockIdx.x * blockDim.x + threadIdx.x;
    if (idx >= T2_ELEMS) return;
    int e  = idx & 31;
    int k2 = (idx >> 5) & 15;
    int d  = idx >> 9;
    float s0 = 0.0f, s1 = 0.0f;
#pragma unroll
    for (int h = 0; h < H; ++h) {
        float ev = edge_table[e * H + h];
        s0 += ev * W[d * (H * H) + h * H + (2 * k2)];
        s1 += ev * W[d * (H * H) + h * H + (2 * k2 + 1)];
    }
    g_T2[idx] = __floats2half2_rn(s0, s1);
}

__global__ __launch_bounds__(256)
void bond_encoding_kernel(const int* __restrict__ spatial_pos,
                          const int* __restrict__ edge_input,
                          const float* __restrict__ spd_table,
                          float* __restrict__ out) {
    extern __shared__ float sh[];
    __half2* shT = (__half2*)sh;          // 8192 half2: [d][k2][e]
    float*   shS = sh + T2_ELEMS;         // 2048 floats: spd transposed [k][sp]

    // Stage T (32KB, vectorized)
    {
        const float4* src = (const float4*)g_T2;
        float4* dst = (float4*)shT;
#pragma unroll
        for (int i = threadIdx.x; i < T2_ELEMS / 4; i += 256)
            dst[i] = src[i];
    }
    // Stage spd transposed: shS[k*64 + sp] = spd_table[sp*32 + k]
    // (bank = sp mod 32; only sp and sp+32 share a bank -> degree <= 2)
    for (int i = threadIdx.x; i < SPD_ELEMS; i += 256) {
        int sp = i >> 5;
        int k  = i & 31;
        shS[k * NSPAT + sp] = spd_table[i];
    }
    __syncthreads();

    for (int task = blockIdx.x; task < N_TASKS; task += GRID) {
        int tile = task >> 1;
        int kh   = task & 1;                 // k-half: 0 -> k 0..15, 1 -> 16..31
        int pair = tile * 256 + threadIdx.x; // pair = i*512 + j

        // 16 edge indices (each < 32) packed into 4 byte-packed regs
        const int4* ep = (const int4*)(edge_input) + pair * 4;
        int4 v0 = ep[0], v1 = ep[1], v2 = ep[2], v3 = ep[3];
        unsigned pk[4];
        pk[0] = (unsigned)v0.x | ((unsigned)v0.y << 8) | ((unsigned)v0.z << 16) | ((unsigned)v0.w << 24);
        pk[1] = (unsigned)v1.x | ((unsigned)v1.y << 8) | ((unsigned)v1.z << 16) | ((unsigned)v1.w << 24);
        pk[2] = (unsigned)v2.x | ((unsigned)v2.y << 8) | ((unsigned)v2.z << 16) | ((unsigned)v2.w << 24);
        pk[3] = (unsigned)v3.x | ((unsigned)v3.y << 8) | ((unsigned)v3.z << 16) | ((unsigned)v3.w << 24);

        float acc[16];
#pragma unroll
        for (int k = 0; k < 16; ++k) acc[k] = 0.0f;

#pragma unroll
        for (int d = 0; d < MAXD; ++d) {
            unsigned e = (pk[d >> 2] >> ((d & 3) * 8)) & 0xFFu;
            const __half2* p = shT + (d * 16 + kh * 8) * 32 + e;
#pragma unroll
            for (int j = 0; j < 8; ++j) {
                float2 f = __half22float2(p[j * 32]);
                acc[2 * j]     += f.x;
                acc[2 * j + 1] += f.y;
            }
        }

        int sp = spatial_pos[pair];
        float rden = (sp == 0) ? 1.0f : (1.0f / (float)sp);
        int kbase = kh * 16;

#pragma unroll
        for (int k = 0; k < 16; ++k) {
            __stcs(&out[(kbase + k) * PAIRS + pair], shS[(kbase + k) * NSPAT + sp]);
            __stcs(&out[H * PAIRS + (kbase + k) * PAIRS + pair], acc[k] * rden);
        }
    }
}

extern "C" void kernel_launch(void* const* d_in, const int* in_sizes, int n_in,
                              void* d_out, int out_size) {
    const int*   spatial_pos = nullptr;
    const int*   edge_input  = nullptr;
    const float* spd_table   = nullptr;
    const float* edge_table  = nullptr;
    const float* W           = nullptr;
    for (int i = 0; i < n_in; ++i) {
        switch (in_sizes[i]) {
            case PAIRS:          spatial_pos = (const int*)d_in[i];   break;
            case PAIRS * MAXD:   edge_input  = (const int*)d_in[i];   break;
            case SPD_ELEMS:      spd_table   = (const float*)d_in[i]; break;
            case H * H:          edge_table  = (const float*)d_in[i]; break;
            case NSPAT * H * H:  W           = (const float*)d_in[i]; break;
            default: break;
        }
    }

    precompute_T_kernel<<<(T2_ELEMS + 255) / 256, 256>>>(edge_table, W);

    cudaFuncSetAttribute(bond_encoding_kernel,
                         cudaFuncAttributeMaxDynamicSharedMemorySize, SMEM_BYTES);
    bond_encoding_kernel<<<GRID, 256, SMEM_BYTES>>>(
        spatial_pos, edge_input, spd_table, (float*)d_out);
}

// round 3
// speedup vs baseline: 1.1171x; 1.0130x over previous
#include <cuda_runtime.h>
#include <cuda_fp16.h>

// ---------------------------------------------------------------------------
// N=512, MAX_DIST=16, H=32, N_SPATIAL=64, BOND_TYPES=32.
// edge_sum[i,j,k] = sum_d T[d][edge_input[i,j,d]][k],  T[d] = edge_table @ W[d]
// T precomputed fp32, stored half2 over k: g_T2[d*512 + k2*32 + e] (bank = e ->
// conflict-free gather). Accumulation: 4-deep fp16 pairwise tree per d-group,
// one fp32 FFMA (folding 1/sp) per group. Indices pre-packed (<<2) into one
// uint4 per pair. Tasks = (256-pair tile) x (k-quarter) = 4096 over 888 blocks.
// ---------------------------------------------------------------------------

#define NN        512
#define PAIRS     (NN * NN)          // 262144
#define MAXD      16
#define H         32
#define NSPAT     64
#define T2_ELEMS  (MAXD * 16 * 32)   // 8192 half2 = 32KB
#define SHS_ELEMS (16 * NSPAT)       // 1024 half2 = 4KB
#define SMEM_BYTES ((T2_ELEMS + SHS_ELEMS) * 4)   // 36864
#define GRID      888               // 6 blocks/SM * 148 SMs
#define N_TASKS   4096              // 1024 tiles * 4 k-quarters

__device__ __half2 g_T2[T2_ELEMS];
__device__ uint4   g_packed[PAIRS];  // 16 indices, pre-scaled by 4, one byte each

__global__ void precompute_T_kernel(const float* __restrict__ edge_table,
                                    const float* __restrict__ W) {
    int idx = blockIdx.x * blockDim.x + threadIdx.x;
    if (idx >= T2_ELEMS) return;
    int e  = idx & 31;
    int k2 = (idx >> 5) & 15;
    int d  = idx >> 9;
    float s0 = 0.0f, s1 = 0.0f;
#pragma unroll
    for (int h = 0; h < H; ++h) {
        float ev = edge_table[e * H + h];
        s0 += ev * W[d * (H * H) + h * H + (2 * k2)];
        s1 += ev * W[d * (H * H) + h * H + (2 * k2 + 1)];
    }
    g_T2[idx] = __floats2half2_rn(s0, s1);
}

__global__ __launch_bounds__(256)
void pack_edges_kernel(const int* __restrict__ edge_input) {
    int pair = blockIdx.x * 256 + threadIdx.x;
    const int4* ep = (const int4*)edge_input + pair * 4;
    int4 a = ep[0], b = ep[1], c = ep[2], d = ep[3];
    uint4 r;
    r.x = ((unsigned)a.x << 2) | ((unsigned)a.y << 10) | ((unsigned)a.z << 18) | ((unsigned)a.w << 26);
    r.y = ((unsigned)b.x << 2) | ((unsigned)b.y << 10) | ((unsigned)b.z << 18) | ((unsigned)b.w << 26);
    r.z = ((unsigned)c.x << 2) | ((unsigned)c.y << 10) | ((unsigned)c.z << 18) | ((unsigned)c.w << 26);
    r.w = ((unsigned)d.x << 2) | ((unsigned)d.y << 10) | ((unsigned)d.z << 18) | ((unsigned)d.w << 26);
    g_packed[pair] = r;
}

__global__ __launch_bounds__(256, 6)
void bond_encoding_kernel(const int* __restrict__ spatial_pos,
                          const float* __restrict__ spd_table,
                          float* __restrict__ out) {
    extern __shared__ float sh[];
    __half2* shT = (__half2*)sh;              // [d][k2][e], 32KB
    __half2* shS = (__half2*)sh + T2_ELEMS;   // [k2][sp],   4KB

    // Stage T (vectorized, coalesced)
    {
        const float4* src = (const float4*)g_T2;
        float4* dst = (float4*)shT;
#pragma unroll
        for (int i = threadIdx.x; i < T2_ELEMS / 4; i += 256)
            dst[i] = src[i];
    }
    // Stage spd transposed as half2: shS[k2*64 + sp] (bank = sp -> <=2-way)
    for (int i = threadIdx.x; i < SHS_ELEMS; i += 256) {
        int k2 = i >> 6;
        int sp = i & 63;
        shS[i] = __floats2half2_rn(spd_table[sp * H + 2 * k2],
                                   spd_table[sp * H + 2 * k2 + 1]);
    }
    __syncthreads();

    for (int task = blockIdx.x; task < N_TASKS; task += GRID) {
        int tile = task >> 2;
        int kq   = task & 3;                  // k-quarter: 8 heads
        int pair = tile * 256 + threadIdx.x;

        uint4 pk4 = g_packed[pair];           // one LDG.128: all 16 indices *4
        unsigned pk[4] = { pk4.x, pk4.y, pk4.z, pk4.w };

        int sp = __ldg(spatial_pos + pair);
        float rden = (sp == 0) ? 1.0f : (1.0f / (float)sp);

        float acc[8];
#pragma unroll
        for (int j = 0; j < 8; ++j) acc[j] = 0.0f;

#pragma unroll
        for (int g = 0; g < 4; ++g) {         // d-group of 4: d = 4g..4g+3
            // byte base for d=4g at this k-quarter
            const char* base = (const char*)(shT + ((4 * g) * 16 + kq * 4) * 32);
            unsigned o0 =  pk[g]        & 0xFCu;     // e*4 (byte offset)
            unsigned o1 = (pk[g] >> 8)  & 0xFCu;
            unsigned o2 = (pk[g] >> 16) & 0xFCu;
            unsigned o3 = (pk[g] >> 24);             // already aligned, <=0x7C
            const __half2* p0 = (const __half2*)(base          + o0);
            const __half2* p1 = (const __half2*)(base + 2048   + o1);
            const __half2* p2 = (const __half2*)(base + 4096   + o2);
            const __half2* p3 = (const __half2*)(base + 6144   + o3);
#pragma unroll
            for (int j = 0; j < 4; ++j) {     // 4 k2 slots in this quarter
                __half2 t = __hadd2(__hadd2(p0[j * 32], p1[j * 32]),
                                    __hadd2(p2[j * 32], p3[j * 32]));
                float2 f = __half22float2(t);
                acc[2 * j]     = fmaf(f.x, rden, acc[2 * j]);
                acc[2 * j + 1] = fmaf(f.y, rden, acc[2 * j + 1]);
            }
        }

        int k0 = kq * 8;
#pragma unroll
        for (int j = 0; j < 4; ++j) {
            float2 sf = __half22float2(shS[(kq * 4 + j) * NSPAT + sp]);
            int k = k0 + 2 * j;
            __stcs(out + k * PAIRS + pair,                 sf.x);
            __stcs(out + (k + 1) * PAIRS + pair,           sf.y);
            __stcs(out + (H + k) * PAIRS + pair,           acc[2 * j]);
            __stcs(out + (H + k + 1) * PAIRS + pair,       acc[2 * j + 1]);
        }
    }
}

extern "C" void kernel_launch(void* const* d_in, const int* in_sizes, int n_in,
                              void* d_out, int out_size) {
    const int*   spatial_pos = nullptr;
    const int*   edge_input  = nullptr;
    const float* spd_table   = nullptr;
    const float* edge_table  = nullptr;
    const float* W           = nullptr;
    for (int i = 0; i < n_in; ++i) {
        switch (in_sizes[i]) {
            case PAIRS:          spatial_pos = (const int*)d_in[i];   break;
            case PAIRS * MAXD:   edge_input  = (const int*)d_in[i];   break;
            case NSPAT * H:      spd_table   = (const float*)d_in[i]; break;
            case H * H:          edge_table  = (const float*)d_in[i]; break;
            case NSPAT * H * H:  W           = (const float*)d_in[i]; break;
            default: break;
        }
    }

    precompute_T_kernel<<<T2_ELEMS / 256, 256>>>(edge_table, W);
    pack_edges_kernel<<<PAIRS / 256, 256>>>(edge_input);

    cudaFuncSetAttribute(bond_encoding_kernel,
                         cudaFuncAttributeMaxDynamicSharedMemorySize, SMEM_BYTES);
    bond_encoding_kernel<<<GRID, 256, SMEM_BYTES>>>(
        spatial_pos, spd_table, (float*)d_out);
}

// round 4
// speedup vs baseline: 1.3103x; 1.1729x over previous
#include <cuda_runtime.h>
#include <cuda_fp16.h>

// ---------------------------------------------------------------------------
// N=512, MAX_DIST=16, H=32, N_SPATIAL=64, BOND_TYPES=32.
// edge_sum[i,j,k] = sum_d T[d][edge_input[i,j,d]][k],  T[d] = edge_table @ W[d]
// Prologue fused into ONE kernel: blocks 0..15 compute T[d] (fp32 math, stored
// half2 over k in g_T2, smem-staged operands), blocks 16..527 pack the 16
// per-pair edge indices (pre-scaled x4) into one uint4. Main kernel: per-task
// (256-pair tile x k-quarter) gather-accumulate with fp16 pairwise tree,
// conflict-free smem layout (bank = e), fully coalesced streaming stores.
// ---------------------------------------------------------------------------

#define NN        512
#define PAIRS     (NN * NN)          // 262144
#define MAXD      16
#define H         32
#define NSPAT     64
#define T2_ELEMS  (MAXD * 16 * 32)   // 8192 half2 = 32KB
#define SHS_ELEMS (16 * NSPAT)       // 1024 half2 = 4KB
#define SMEM_BYTES ((T2_ELEMS + SHS_ELEMS) * 4)   // 36864
#define GRID      888               // 6 blocks/SM * 148 SMs
#define N_TASKS   4096              // 1024 tiles * 4 k-quarters

__device__ __half2 g_T2[T2_ELEMS];
__device__ uint4   g_packed[PAIRS];  // 16 indices, pre-scaled by 4, one byte each

// Blocks 0..15: T[d] precompute (one block per d). Blocks 16..527: pack.
__global__ __launch_bounds__(512)
void prep_kernel(const float* __restrict__ edge_table,
                 const float* __restrict__ W,
                 const int* __restrict__ edge_input) {
    __shared__ float shE[H * H];   // [h][e] = edge_table[e][h]
    __shared__ float shW[H * H];   // W[d] row-major [h][k]
    int t = threadIdx.x;

    if (blockIdx.x < MAXD) {
        int d = blockIdx.x;
        // Stage edge_table transposed + W[d] (coalesced LDG; STS conflicts trivial)
        for (int i = t; i < H * H; i += 512) {
            int e = i >> 5, h = i & 31;
            shE[h * H + e] = edge_table[i];
            shW[i] = W[d * (H * H) + i];
        }
        __syncthreads();
        if (t < 512) {
            int e  = t & 31;        // = lane -> shE bank e, conflict-free
            int k2 = t >> 5;        // uniform per warp -> shW broadcast
            float s0 = 0.0f, s1 = 0.0f;
#pragma unroll
            for (int h = 0; h < H; ++h) {
                float ev = shE[h * H + e];
                s0 += ev * shW[h * H + 2 * k2];
                s1 += ev * shW[h * H + 2 * k2 + 1];
            }
            g_T2[d * 512 + k2 * 32 + e] = __floats2half2_rn(s0, s1);
        }
    } else {
        int pair = (blockIdx.x - MAXD) * 512 + t;   // 512 blocks x 512 = PAIRS
        const int4* ep = (const int4*)edge_input + pair * 4;
        int4 a = ep[0], b = ep[1], c = ep[2], e4 = ep[3];
        uint4 r;
        r.x = ((unsigned)a.x << 2) | ((unsigned)a.y << 10) | ((unsigned)a.z << 18) | ((unsigned)a.w << 26);
        r.y = ((unsigned)b.x << 2) | ((unsigned)b.y << 10) | ((unsigned)b.z << 18) | ((unsigned)b.w << 26);
        r.z = ((unsigned)c.x << 2) | ((unsigned)c.y << 10) | ((unsigned)c.z << 18) | ((unsigned)c.w << 26);
        r.w = ((unsigned)e4.x << 2) | ((unsigned)e4.y << 10) | ((unsigned)e4.z << 18) | ((unsigned)e4.w << 26);
        g_packed[pair] = r;
    }
}

__global__ __launch_bounds__(256, 6)
void bond_encoding_kernel(const int* __restrict__ spatial_pos,
                          const float* __restrict__ spd_table,
                          float* __restrict__ out) {
    extern __shared__ float sh[];
    __half2* shT = (__half2*)sh;              // [d][k2][e], 32KB
    __half2* shS = (__half2*)sh + T2_ELEMS;   // [k2][sp],   4KB

    {
        const float4* src = (const float4*)g_T2;
        float4* dst = (float4*)shT;
#pragma unroll
        for (int i = threadIdx.x; i < T2_ELEMS / 4; i += 256)
            dst[i] = src[i];
    }
    for (int i = threadIdx.x; i < SHS_ELEMS; i += 256) {
        int k2 = i >> 6;
        int sp = i & 63;
        shS[i] = __floats2half2_rn(spd_table[sp * H + 2 * k2],
                                   spd_table[sp * H + 2 * k2 + 1]);
    }
    __syncthreads();

    for (int task = blockIdx.x; task < N_TASKS; task += GRID) {
        int tile = task >> 2;
        int kq   = task & 3;                  // k-quarter: 8 heads
        int pair = tile * 256 + threadIdx.x;

        uint4 pk4 = g_packed[pair];           // one LDG.128: all 16 indices *4
        unsigned pk[4] = { pk4.x, pk4.y, pk4.z, pk4.w };

        int sp = __ldg(spatial_pos + pair);
        float rden = (sp == 0) ? 1.0f : (1.0f / (float)sp);

        float acc[8];
#pragma unroll
        for (int j = 0; j < 8; ++j) acc[j] = 0.0f;

#pragma unroll
        for (int g = 0; g < 4; ++g) {         // d-group of 4: d = 4g..4g+3
            const char* base = (const char*)(shT + ((4 * g) * 16 + kq * 4) * 32);
            unsigned o0 =  pk[g]        & 0xFCu;
            unsigned o1 = (pk[g] >> 8)  & 0xFCu;
            unsigned o2 = (pk[g] >> 16) & 0xFCu;
            unsigned o3 = (pk[g] >> 24);
            const __half2* p0 = (const __half2*)(base          + o0);
            const __half2* p1 = (const __half2*)(base + 2048   + o1);
            const __half2* p2 = (const __half2*)(base + 4096   + o2);
            const __half2* p3 = (const __half2*)(base + 6144   + o3);
#pragma unroll
            for (int j = 0; j < 4; ++j) {
                __half2 tt = __hadd2(__hadd2(p0[j * 32], p1[j * 32]),
                                     __hadd2(p2[j * 32], p3[j * 32]));
                float2 f = __half22float2(tt);
                acc[2 * j]     = fmaf(f.x, rden, acc[2 * j]);
                acc[2 * j + 1] = fmaf(f.y, rden, acc[2 * j + 1]);
            }
        }

        int k0 = kq * 8;
#pragma unroll
        for (int j = 0; j < 4; ++j) {
            float2 sf = __half22float2(shS[(kq * 4 + j) * NSPAT + sp]);
            int k = k0 + 2 * j;
            __stcs(out + k * PAIRS + pair,           sf.x);
            __stcs(out + (k + 1) * PAIRS + pair,     sf.y);
            __stcs(out + (H + k) * PAIRS + pair,     acc[2 * j]);
            __stcs(out + (H + k + 1) * PAIRS + pair, acc[2 * j + 1]);
        }
    }
}

extern "C" void kernel_launch(void* const* d_in, const int* in_sizes, int n_in,
                              void* d_out, int out_size) {
    const int*   spatial_pos = nullptr;
    const int*   edge_input  = nullptr;
    const float* spd_table   = nullptr;
    const float* edge_table  = nullptr;
    const float* W           = nullptr;
    for (int i = 0; i < n_in; ++i) {
        switch (in_sizes[i]) {
            case PAIRS:          spatial_pos = (const int*)d_in[i];   break;
            case PAIRS * MAXD:   edge_input  = (const int*)d_in[i];   break;
            case NSPAT * H:      spd_table   = (const float*)d_in[i]; break;
            case H * H:          edge_table  = (const float*)d_in[i]; break;
            case NSPAT * H * H:  W           = (const float*)d_in[i]; break;
            default: break;
        }
    }

    prep_kernel<<<MAXD + PAIRS / 512, 512>>>(edge_table, W, edge_input);

    cudaFuncSetAttribute(bond_encoding_kernel,
                         cudaFuncAttributeMaxDynamicSharedMemorySize, SMEM_BYTES);
    bond_encoding_kernel<<<GRID, 256, SMEM_BYTES>>>(
        spatial_pos, spd_table, (float*)d_out);
}